// round 11
// baseline (speedup 1.0000x reference)
#include <cuda_runtime.h>
#include <cuda_fp16.h>
#include <cstdint>

#define BB   32
#define CC   64
#define HH   128
#define WW   128
#define OUTC 64
#define HID  128

// NHWC planes with halo rows: per (b,h): 130 rows (w=-1..128) x 64 c, fp16
#define PROW   64                 // elems per row (128B)
#define PSIZE  (130 * PROW)       // 8320 elems per plane
#define PBYTES (PSIZE * 2)
// Weights per (b, o-half): [9 tap][64 c][32 o'] fp16 = 18432 elems
#define WTILE  (64 * 32)
#define WSLICE (9 * WTILE)        // 18432

// ---------------------------------------------------------------------------
// Device scratch (static globals — no allocation allowed)
// ---------------------------------------------------------------------------
__device__ float g_stats[BB * CC];
__device__ float g_hiddenT[HID * BB];       // transposed: [k][sample]
__device__ __align__(128) uint16_t g_wt[(size_t)BB * 2 * WSLICE];
__device__ __align__(128) uint16_t g_xhi[(size_t)BB * HH * PSIZE];

// ---------------------------------------------------------------------------
// PTX helpers
// ---------------------------------------------------------------------------
__device__ __forceinline__ uint32_t smem_u32(const void* p) {
    uint32_t a;
    asm("{ .reg .u64 t; cvta.to.shared.u64 t, %1; cvt.u32.u64 %0, t; }" : "=r"(a) : "l"(p));
    return a;
}
#define MBAR_INIT(a, n) asm volatile("mbarrier.init.shared.b64 [%0], %1;" :: "r"(a), "r"(n) : "memory")
#define MBAR_EXPECT_TX(a, b) asm volatile("mbarrier.arrive.expect_tx.shared.b64 _, [%0], %1;" :: "r"(a), "r"(b) : "memory")
#define MBAR_WAIT(a, ph) do {                                                         \
    uint32_t _m = (a), _p = (ph), _d;                                                 \
    asm volatile("{\n\t.reg .pred p;\n\t"                                             \
        "mbarrier.try_wait.parity.acquire.cta.shared::cta.b64 p, [%1], %2;\n\t"       \
        "selp.b32 %0, 1, 0, p;\n\t}" : "=r"(_d) : "r"(_m), "r"(_p) : "memory");       \
    if (!_d) {                                                                        \
        asm volatile("{\n\t.reg .pred P1;\n\t"                                        \
            "WL_%=:\n\t"                                                              \
            "mbarrier.try_wait.parity.acquire.cta.shared::cta.b64 P1, [%0], %1, 0x989680;\n\t" \
            "@P1 bra.uni WD_%=;\n\t"                                                  \
            "bra.uni WL_%=;\n\t"                                                      \
            "WD_%=:\n\t}" :: "r"(_m), "r"(_p) : "memory");                            \
    }                                                                                 \
} while (0)
#define BULK_G2S(dst, src, bytes, mbar)                                               \
    asm volatile("cp.async.bulk.shared::cta.global.mbarrier::complete_tx::bytes "      \
                 "[%0], [%1], %2, [%3];"                                               \
                 :: "r"(dst), "l"(src), "r"(bytes), "r"(mbar) : "memory")

__device__ __forceinline__ void ldm_x4(uint32_t* r, uint32_t addr) {
    asm volatile("ldmatrix.sync.aligned.m8n8.x4.shared.b16 {%0,%1,%2,%3}, [%4];"
                 : "=r"(r[0]), "=r"(r[1]), "=r"(r[2]), "=r"(r[3]) : "r"(addr));
}
__device__ __forceinline__ void ldm_x4_t(uint32_t* r, uint32_t addr) {
    asm volatile("ldmatrix.sync.aligned.m8n8.x4.trans.shared.b16 {%0,%1,%2,%3}, [%4];"
                 : "=r"(r[0]), "=r"(r[1]), "=r"(r[2]), "=r"(r[3]) : "r"(addr));
}
__device__ __forceinline__ void mma_f16(float* d, const uint32_t* a, const uint32_t* b) {
    asm volatile("mma.sync.aligned.m16n8k16.row.col.f32.f16.f16.f32 "
                 "{%0,%1,%2,%3}, {%4,%5,%6,%7}, {%8,%9}, {%0,%1,%2,%3};"
                 : "+f"(d[0]), "+f"(d[1]), "+f"(d[2]), "+f"(d[3])
                 : "r"(a[0]), "r"(a[1]), "r"(a[2]), "r"(a[3]), "r"(b[0]), "r"(b[1]));
}

// ---------------------------------------------------------------------------
__global__ void zero_stats_kernel() {
    g_stats[blockIdx.x * 256 + threadIdx.x] = 0.f;
}

// ---------------------------------------------------------------------------
// Kernel 1: prep — NCHW fp32 -> halo'd NHWC fp16 (chunk-swizzled) + sums
// grid (h=128, b=32), 256 threads.
// ---------------------------------------------------------------------------
__global__ __launch_bounds__(256) void prep_kernel(const float* __restrict__ x) {
    int h = blockIdx.x, b = blockIdx.y;
    __shared__ float s[CC * 129];
    const float* xb = x + (size_t)b * CC * HH * WW + (size_t)h * WW;
    int t = threadIdx.x;
#pragma unroll
    for (int i = 0; i < 32; ++i) {
        int idx = i * 256 + t;
        int c = idx >> 7, w = idx & 127;
        s[c * 129 + w] = xb[(size_t)c * (HH * WW) + w];
    }
    __syncthreads();
    if (t < CC) {
        float sum = 0.f;
#pragma unroll 8
        for (int w = 0; w < WW; ++w) sum += s[t * 129 + w];
        atomicAdd(&g_stats[b * CC + t], sum);
    }
    int w = t >> 1, half = t & 1;
    __align__(16) uint16_t hbuf[32];
#pragma unroll
    for (int e = 0; e < 32; ++e) {
        __half hv = __float2half_rn(s[(half * 32 + e) * 129 + w]);
        hbuf[e] = *reinterpret_cast<uint16_t*>(&hv);
    }
    size_t rowbase = ((size_t)b * HH + h) * PSIZE + (size_t)(w + 1) * PROW;
    uint16_t* dh = g_xhi + rowbase;
    int ph = (w + 1) & 7;
#pragma unroll
    for (int g = 0; g < 4; ++g) {
        int chunk = (half * 4 + g) ^ ph;
        *reinterpret_cast<uint4*>(dh + chunk * 8) = *reinterpret_cast<const uint4*>(hbuf + g * 8);
    }
    if (t < 16) {
        int reg = t >> 3, ch = t & 7;
        uint16_t* base = g_xhi + ((size_t)b * HH + h) * PSIZE
                       + (reg ? (size_t)129 * PROW : 0) + ch * 8;
        *reinterpret_cast<uint4*>(base) = make_uint4(0u, 0u, 0u, 0u);
    }
}

// ---------------------------------------------------------------------------
// Kernel 2: hiddenT[k][b] = relu(mean @ W1 + b1)
// ---------------------------------------------------------------------------
__global__ void hidden_kernel(const float* __restrict__ W1, const float* __restrict__ b1) {
    int b = blockIdx.x;
    __shared__ float s[CC];
    if (threadIdx.x < CC) s[threadIdx.x] = g_stats[b * CC + threadIdx.x] * (1.0f / (HH * WW));
    __syncthreads();
    int h = threadIdx.x;
    float acc = b1[h];
#pragma unroll 8
    for (int c = 0; c < CC; ++c) acc += s[c] * W1[c * HID + h];
    g_hiddenT[h * BB + b] = fmaxf(acc, 0.0f);
}

// ---------------------------------------------------------------------------
// Kernel 3: wgen — per-sample weights -> fp16, layout [b][oh][tap][c][o']
// o' chunk-swizzled: o' = ((ol>>3)^(c&3))*8+(ol&7)
// W2 column j = o*(CC*9) + c*9 + k.
// grid (72, 2), 256 thr; 2 cols x 16 samples per thread.  W2 read only 2x.
// 72 blocks x 512 cols = 36864 = WSZ exactly.
// ---------------------------------------------------------------------------
__global__ __launch_bounds__(256) void wgen_kernel(const float* __restrict__ W2, const float* __restrict__ b2) {
    __shared__ __align__(16) float sh[HID][16];
    int b0 = blockIdx.y * 16;
    for (int i = threadIdx.x; i < HID * 16; i += 256)
        sh[i >> 4][i & 15] = g_hiddenT[(i >> 4) * BB + b0 + (i & 15)];
    __syncthreads();

    int j0 = blockIdx.x * 512 + threadIdx.x * 2;
    float2 acc[16];
#pragma unroll
    for (int bb = 0; bb < 16; ++bb) acc[bb] = make_float2(0.f, 0.f);

#pragma unroll 2
    for (int k = 0; k < HID; ++k) {
        float2 wv = *reinterpret_cast<const float2*>(&W2[(size_t)k * (OUTC * CC * 9) + j0]);
        float4 h0 = *reinterpret_cast<const float4*>(&sh[k][0]);
        float4 h1 = *reinterpret_cast<const float4*>(&sh[k][4]);
        float4 h2 = *reinterpret_cast<const float4*>(&sh[k][8]);
        float4 h3 = *reinterpret_cast<const float4*>(&sh[k][12]);
        const float hv[16] = {h0.x, h0.y, h0.z, h0.w, h1.x, h1.y, h1.z, h1.w,
                              h2.x, h2.y, h2.z, h2.w, h3.x, h3.y, h3.z, h3.w};
#pragma unroll
        for (int bb = 0; bb < 16; ++bb) {
            acc[bb].x = fmaf(hv[bb], wv.x, acc[bb].x);
            acc[bb].y = fmaf(hv[bb], wv.y, acc[bb].y);
        }
    }
    float2 bias = *reinterpret_cast<const float2*>(&b2[j0]);
    int o[2], cdec[2], kdec[2];
#pragma unroll
    for (int q = 0; q < 2; ++q) {
        int j = j0 + q;
        o[q] = j / (CC * 9);
        int rem = j % (CC * 9);
        cdec[q] = rem / 9;
        kdec[q] = rem % 9;
    }
#pragma unroll
    for (int bb = 0; bb < 16; ++bb) {
        float vals[2] = {acc[bb].x + bias.x, acc[bb].y + bias.y};
#pragma unroll
        for (int q = 0; q < 2; ++q) {
            __half hv = __float2half_rn(vals[q]);
            int oh = o[q] >> 5, ol = o[q] & 31;
            int op = (((ol >> 3) ^ (cdec[q] & 3)) << 3) | (ol & 7);
            size_t base = ((((size_t)(b0 + bb) * 2 + oh) * 9 + kdec[q]) * 64 + cdec[q]) * 32 + op;
            g_wt[base] = *reinterpret_cast<uint16_t*>(&hv);
        }
    }
}

// ---------------------------------------------------------------------------
// Kernel 4: conv as implicit GEMM on mma.sync fp16, single pass, w-split.
// grid (oh*wh=4, htile=16, b=32), 128 threads (4 warps), 3 CTAs/SM.
// CTA covers 64 w (wh half) x 32 o (oh half) x 8 h rows.
// Plane slot = 66 rows x 128B = 8448B (storage rows W0..W0+65, W0 = wh*64).
// ---------------------------------------------------------------------------
#define SM_W     128
#define SM_X     (128 + 36864)           // 36992
#define SLOT     (66 * 128)              // 8448
#define SM_TOTAL (36992 + 4 * SLOT)      // 70784

__global__ __launch_bounds__(128, 3)
void conv_kernel(float* __restrict__ out) {
    extern __shared__ char smem[];
    uint32_t sb = smem_u32(smem);
    int b = blockIdx.z;
    int h0 = blockIdx.y * 8;
    int oh = blockIdx.x & 1, wh = blockIdx.x >> 1;
    int o0 = oh * 32, W0 = wh * 64;
    int tid = threadIdx.x;
    int lane = tid & 31, wid = tid >> 5;

    if (tid == 0) {
        MBAR_INIT(sb, 1);
        asm volatile("fence.proxy.async.shared::cta;" ::: "memory");
    }
    __syncthreads();

    const uint16_t* xh = g_xhi + (size_t)b * HH * PSIZE + (size_t)W0 * PROW;

    // prologue: weights + planes h0-1..h0+1 (66-row windows)
    if (tid == 0) {
        uint32_t bytes = 2 * WSLICE;
        for (int d = 0; d < 3; ++d) {
            int p = h0 - 1 + d;
            if (p >= 0 && p < HH) bytes += SLOT;
        }
        MBAR_EXPECT_TX(sb, bytes);
        BULK_G2S(sb + SM_W, g_wt + ((size_t)b * 2 + oh) * WSLICE, 2u * WSLICE, sb);
        for (int d = 0; d < 3; ++d) {
            int p = h0 - 1 + d;
            if (p < 0 || p >= HH) continue;
            BULK_G2S(sb + SM_X + (uint32_t)(p & 3) * SLOT, xh + (size_t)p * PSIZE, (uint32_t)SLOT, sb);
        }
    }

    int lph = 0;
    bool pending = true;
    int w0 = wid * 16;
    int r7 = lane & 7, half = (lane >> 3) & 1, quad = lane >> 4, l3 = lane & 3;
    int rbase = r7 + half * 8;

    for (int hh = 0; hh < 8; ++hh) {
        int h = h0 + hh;
        if (pending) { MBAR_WAIT(sb, lph); lph ^= 1; }
        __syncthreads();

        pending = (hh < 7) && (h + 2 < HH);
        if (pending && tid == 0) {
            MBAR_EXPECT_TX(sb, (uint32_t)SLOT);
            int p = h + 2;
            BULK_G2S(sb + SM_X + (uint32_t)(p & 3) * SLOT, xh + (size_t)p * PSIZE, (uint32_t)SLOT, sb);
        }

        float acc[4][4];
#pragma unroll
        for (int nt = 0; nt < 4; ++nt)
#pragma unroll
            for (int q = 0; q < 4; ++q) acc[nt][q] = 0.f;

        for (int dr = 0; dr < 3; ++dr) {
            int p = h - 1 + dr;
            if ((unsigned)p >= (unsigned)HH) continue;
            uint32_t pb = sb + SM_X + (uint32_t)(p & 3) * SLOT;
#pragma unroll
            for (int dc = 0; dc < 3; ++dc) {
                uint32_t bt = sb + SM_W + (uint32_t)(dr * 3 + dc) * 4096u;
                int srow = w0 + dc + rbase;           // local row (W0-relative)
                uint32_t abase = pb + (uint32_t)srow * 128u;
                int ax = srow & 7;                    // W0 % 8 == 0 -> phase identical
#pragma unroll
                for (int ks = 0; ks < 4; ++ks) {
                    uint32_t ah[4], bh[8];
                    ldm_x4(ah, abase + (uint32_t)((((ks << 1) | quad) ^ ax) << 4));
                    uint32_t brow = bt + (uint32_t)((ks * 16 + rbase) * 64);
                    ldm_x4_t(bh,     brow + (uint32_t)(((0 | quad) ^ l3) << 4));
                    ldm_x4_t(bh + 4, brow + (uint32_t)(((2 | quad) ^ l3) << 4));
#pragma unroll
                    for (int nt = 0; nt < 4; ++nt)
                        mma_f16(acc[nt], ah, bh + nt * 2);
                }
            }
        }

        int wcol = W0 + w0 + (lane >> 2);
#pragma unroll
        for (int nt = 0; nt < 4; ++nt) {
            int o = o0 + nt * 8 + l3 * 2;
            float* p0 = out + (((size_t)b * OUTC + o) * HH + h) * WW + wcol;
            float* p1 = p0 + (size_t)HH * WW;
            p0[0] = acc[nt][0];
            p1[0] = acc[nt][1];
            p0[8] = acc[nt][2];
            p1[8] = acc[nt][3];
        }
    }
}

// ---------------------------------------------------------------------------
extern "C" void kernel_launch(void* const* d_in, const int* in_sizes, int n_in,
                              void* d_out, int out_size) {
    const float* x  = (const float*)d_in[0];
    const float* W1 = (const float*)d_in[1];
    const float* b1 = (const float*)d_in[2];
    const float* W2 = (const float*)d_in[3];
    const float* b2 = (const float*)d_in[4];
    float* out = (float*)d_out;

    cudaFuncSetAttribute(conv_kernel, cudaFuncAttributeMaxDynamicSharedMemorySize, SM_TOTAL);

    zero_stats_kernel<<<8, 256>>>();
    prep_kernel<<<dim3(HH, BB), 256>>>(x);
    hidden_kernel<<<BB, HID>>>(W1, b1);
    wgen_kernel<<<dim3(72, 2), 256>>>(W2, b2);
    conv_kernel<<<dim3(4, 16, BB), 128, SM_TOTAL>>>(out);
}

// round 13
// speedup vs baseline: 1.4289x; 1.4289x over previous
#include <cuda_runtime.h>
#include <cuda_fp16.h>
#include <cstdint>

#define BB   32
#define CC   64
#define HH   128
#define WW   128
#define OUTC 64
#define HID  128

// NHWC planes with halo rows: per (b,h): 130 rows (w=-1..128) x 64 c, fp16
#define PROW   64                 // elems per row (128B)
#define PSIZE  (130 * PROW)       // 8320 elems per plane
#define PBYTES (PSIZE * 2)
// Weights per (b, o-half): [9 tap][64 c][32 o'] fp16 = 18432 elems
#define WTILE  (64 * 32)
#define WSLICE (9 * WTILE)        // 18432

// ---------------------------------------------------------------------------
// Device scratch (static globals — no allocation allowed)
// ---------------------------------------------------------------------------
__device__ float g_stats[BB * CC];
__device__ float g_hiddenT[HID * BB];       // transposed: [k][sample]
__device__ __align__(128) uint16_t g_wt[(size_t)BB * 2 * WSLICE];
__device__ __align__(128) uint16_t g_xhi[(size_t)BB * HH * PSIZE];

// ---------------------------------------------------------------------------
// PTX helpers
// ---------------------------------------------------------------------------
__device__ __forceinline__ uint32_t smem_u32(const void* p) {
    uint32_t a;
    asm("{ .reg .u64 t; cvta.to.shared.u64 t, %1; cvt.u32.u64 %0, t; }" : "=r"(a) : "l"(p));
    return a;
}
#define MBAR_INIT(a, n) asm volatile("mbarrier.init.shared.b64 [%0], %1;" :: "r"(a), "r"(n) : "memory")
#define MBAR_EXPECT_TX(a, b) asm volatile("mbarrier.arrive.expect_tx.shared.b64 _, [%0], %1;" :: "r"(a), "r"(b) : "memory")
#define MBAR_WAIT(a, ph) do {                                                         \
    uint32_t _m = (a), _p = (ph), _d;                                                 \
    asm volatile("{\n\t.reg .pred p;\n\t"                                             \
        "mbarrier.try_wait.parity.acquire.cta.shared::cta.b64 p, [%1], %2;\n\t"       \
        "selp.b32 %0, 1, 0, p;\n\t}" : "=r"(_d) : "r"(_m), "r"(_p) : "memory");       \
    if (!_d) {                                                                        \
        asm volatile("{\n\t.reg .pred P1;\n\t"                                        \
            "WL_%=:\n\t"                                                              \
            "mbarrier.try_wait.parity.acquire.cta.shared::cta.b64 P1, [%0], %1, 0x989680;\n\t" \
            "@P1 bra.uni WD_%=;\n\t"                                                  \
            "bra.uni WL_%=;\n\t"                                                      \
            "WD_%=:\n\t}" :: "r"(_m), "r"(_p) : "memory");                            \
    }                                                                                 \
} while (0)
#define BULK_G2S(dst, src, bytes, mbar)                                               \
    asm volatile("cp.async.bulk.shared::cta.global.mbarrier::complete_tx::bytes "      \
                 "[%0], [%1], %2, [%3];"                                               \
                 :: "r"(dst), "l"(src), "r"(bytes), "r"(mbar) : "memory")

__device__ __forceinline__ void ldm_x4(uint32_t* r, uint32_t addr) {
    asm volatile("ldmatrix.sync.aligned.m8n8.x4.shared.b16 {%0,%1,%2,%3}, [%4];"
                 : "=r"(r[0]), "=r"(r[1]), "=r"(r[2]), "=r"(r[3]) : "r"(addr));
}
__device__ __forceinline__ void ldm_x4_t(uint32_t* r, uint32_t addr) {
    asm volatile("ldmatrix.sync.aligned.m8n8.x4.trans.shared.b16 {%0,%1,%2,%3}, [%4];"
                 : "=r"(r[0]), "=r"(r[1]), "=r"(r[2]), "=r"(r[3]) : "r"(addr));
}
__device__ __forceinline__ void mma_f16(float* d, const uint32_t* a, const uint32_t* b) {
    asm volatile("mma.sync.aligned.m16n8k16.row.col.f32.f16.f16.f32 "
                 "{%0,%1,%2,%3}, {%4,%5,%6,%7}, {%8,%9}, {%0,%1,%2,%3};"
                 : "+f"(d[0]), "+f"(d[1]), "+f"(d[2]), "+f"(d[3])
                 : "r"(a[0]), "r"(a[1]), "r"(a[2]), "r"(a[3]), "r"(b[0]), "r"(b[1]));
}

// ---------------------------------------------------------------------------
__global__ void zero_stats_kernel() {
    g_stats[blockIdx.x * 256 + threadIdx.x] = 0.f;
}

// ---------------------------------------------------------------------------
// Kernel 1: prep — NCHW fp32 -> halo'd NHWC fp16 (chunk-swizzled) + sums
// grid (h=128, b=32), 256 threads.
// ---------------------------------------------------------------------------
__global__ __launch_bounds__(256) void prep_kernel(const float* __restrict__ x) {
    int h = blockIdx.x, b = blockIdx.y;
    __shared__ float s[CC * 129];
    const float* xb = x + (size_t)b * CC * HH * WW + (size_t)h * WW;
    int t = threadIdx.x;
#pragma unroll
    for (int i = 0; i < 32; ++i) {
        int idx = i * 256 + t;
        int c = idx >> 7, w = idx & 127;
        s[c * 129 + w] = xb[(size_t)c * (HH * WW) + w];
    }
    __syncthreads();
    if (t < CC) {
        float sum = 0.f;
#pragma unroll 8
        for (int w = 0; w < WW; ++w) sum += s[t * 129 + w];
        atomicAdd(&g_stats[b * CC + t], sum);
    }
    int w = t >> 1, half = t & 1;
    __align__(16) uint16_t hbuf[32];
#pragma unroll
    for (int e = 0; e < 32; ++e) {
        __half hv = __float2half_rn(s[(half * 32 + e) * 129 + w]);
        hbuf[e] = *reinterpret_cast<uint16_t*>(&hv);
    }
    size_t rowbase = ((size_t)b * HH + h) * PSIZE + (size_t)(w + 1) * PROW;
    uint16_t* dh = g_xhi + rowbase;
    int ph = (w + 1) & 7;
#pragma unroll
    for (int g = 0; g < 4; ++g) {
        int chunk = (half * 4 + g) ^ ph;
        *reinterpret_cast<uint4*>(dh + chunk * 8) = *reinterpret_cast<const uint4*>(hbuf + g * 8);
    }
    if (t < 16) {
        int reg = t >> 3, ch = t & 7;
        uint16_t* base = g_xhi + ((size_t)b * HH + h) * PSIZE
                       + (reg ? (size_t)129 * PROW : 0) + ch * 8;
        *reinterpret_cast<uint4*>(base) = make_uint4(0u, 0u, 0u, 0u);
    }
}

// ---------------------------------------------------------------------------
// Kernel 2: hiddenT[k][b] = relu(mean @ W1 + b1)
// ---------------------------------------------------------------------------
__global__ void hidden_kernel(const float* __restrict__ W1, const float* __restrict__ b1) {
    int b = blockIdx.x;
    __shared__ float s[CC];
    if (threadIdx.x < CC) s[threadIdx.x] = g_stats[b * CC + threadIdx.x] * (1.0f / (HH * WW));
    __syncthreads();
    int h = threadIdx.x;
    float acc = b1[h];
#pragma unroll 8
    for (int c = 0; c < CC; ++c) acc += s[c] * W1[c * HID + h];
    g_hiddenT[h * BB + b] = fmaxf(acc, 0.0f);
}

// ---------------------------------------------------------------------------
// Kernel 3: wgen — measured-best shape: grid (72, 4), 256 thr,
// 2 cols x 8 samples per thread.  (288 blocks; W2 read 4x.)
// Layout [b][oh][tap][c][o'], o' chunk-swizzled: o' = ((ol>>3)^(c&3))*8+(ol&7)
// ---------------------------------------------------------------------------
__global__ __launch_bounds__(256) void wgen_kernel(const float* __restrict__ W2, const float* __restrict__ b2) {
    __shared__ float sh[8][HID];
    int b0 = blockIdx.y * 8;
    for (int i = threadIdx.x; i < 8 * HID; i += 256) {
        int s = i >> 7, k = i & 127;
        sh[s][k] = g_hiddenT[k * BB + b0 + s];
    }
    __syncthreads();

    int j0 = blockIdx.x * 512 + threadIdx.x * 2;
    float2 acc[8];
#pragma unroll
    for (int bb = 0; bb < 8; ++bb) acc[bb] = make_float2(0.f, 0.f);

#pragma unroll 4
    for (int k = 0; k < HID; ++k) {
        float2 wv = *reinterpret_cast<const float2*>(&W2[(size_t)k * (OUTC * CC * 9) + j0]);
#pragma unroll
        for (int bb = 0; bb < 8; ++bb) {
            float hv = sh[bb][k];
            acc[bb].x = fmaf(hv, wv.x, acc[bb].x);
            acc[bb].y = fmaf(hv, wv.y, acc[bb].y);
        }
    }
    float2 bias = *reinterpret_cast<const float2*>(&b2[j0]);
    int o[2], cdec[2], kdec[2];
#pragma unroll
    for (int q = 0; q < 2; ++q) {
        int j = j0 + q;
        o[q] = j / (CC * 9);
        int rem = j % (CC * 9);
        cdec[q] = rem / 9;
        kdec[q] = rem % 9;
    }
#pragma unroll
    for (int bb = 0; bb < 8; ++bb) {
        float vals[2] = {acc[bb].x + bias.x, acc[bb].y + bias.y};
#pragma unroll
        for (int q = 0; q < 2; ++q) {
            __half hv = __float2half_rn(vals[q]);
            int oh = o[q] >> 5, ol = o[q] & 31;
            int op = (((ol >> 3) ^ (cdec[q] & 3)) << 3) | (ol & 7);
            size_t base = ((((size_t)(b0 + bb) * 2 + oh) * 9 + kdec[q]) * 64 + cdec[q]) * 32 + op;
            g_wt[base] = *reinterpret_cast<uint16_t*>(&hv);
        }
    }
}

// ---------------------------------------------------------------------------
// Kernel 4: conv as implicit GEMM on mma.sync fp16, h-PAIR blocked.
// grid (oh*wh=4, htile=16, b=32) = 2048 CTAs, 128 threads, 3 CTAs/SM.
// CTA: 64 w x 32 o x 8 h (4 h-pairs).  Per pair: planes h-1..h+2 live,
// B fragments shared across the pair, A fragments shared between rows
// (A(dr,h+1) = A(dr-1,h): same plane+row).  120 ldm + 288 HMMA per pair
// per warp (was 216 ldm + 288 HMMA for 2 rows).
// ---------------------------------------------------------------------------
#define SM_W     128
#define SM_X     (128 + 36864)           // 36992
#define SLOT     (66 * 128)              // 8448
#define SM_TOTAL (36992 + 4 * SLOT)      // 70784

__global__ __launch_bounds__(128, 3)
void conv_kernel(float* __restrict__ out) {
    extern __shared__ char smem[];
    uint32_t sb = smem_u32(smem);
    int b = blockIdx.z;
    int h0 = blockIdx.y * 8;
    int oh = blockIdx.x & 1, wh = blockIdx.x >> 1;
    int o0 = oh * 32, W0 = wh * 64;
    int tid = threadIdx.x;
    int lane = tid & 31, wid = tid >> 5;

    if (tid == 0) {
        MBAR_INIT(sb, 1);
        asm volatile("fence.proxy.async.shared::cta;" ::: "memory");
    }
    __syncthreads();

    const uint16_t* xh = g_xhi + (size_t)b * HH * PSIZE + (size_t)W0 * PROW;

    // prologue: weights + planes h0-1..h0+2 (first pair's working set)
    if (tid == 0) {
        uint32_t bytes = 2 * WSLICE;
        for (int d = 0; d < 4; ++d) {
            int p = h0 - 1 + d;
            if (p >= 0 && p < HH) bytes += SLOT;
        }
        MBAR_EXPECT_TX(sb, bytes);
        BULK_G2S(sb + SM_W, g_wt + ((size_t)b * 2 + oh) * WSLICE, 2u * WSLICE, sb);
        for (int d = 0; d < 4; ++d) {
            int p = h0 - 1 + d;
            if (p < 0 || p >= HH) continue;
            BULK_G2S(sb + SM_X + (uint32_t)(p & 3) * SLOT, xh + (size_t)p * PSIZE, (uint32_t)SLOT, sb);
        }
    }

    int lph = 0;
    bool pending = true;
    int w0 = wid * 16;
    int r7 = lane & 7, half = (lane >> 3) & 1, quad = lane >> 4, l3 = lane & 3;
    int rbase = r7 + half * 8;

    for (int hp = 0; hp < 4; ++hp) {
        int h = h0 + hp * 2;
        if (pending) { MBAR_WAIT(sb, lph); lph ^= 1; }

        bool v0 = (h - 1 >= 0);
        bool v3 = (h + 2 < HH);
        uint32_t pb[4];
#pragma unroll
        for (int q = 0; q < 4; ++q)
            pb[q] = sb + SM_X + (uint32_t)((h - 1 + q) & 3) * SLOT;

        float acc0[4][4], acc1[4][4];
#pragma unroll
        for (int nt = 0; nt < 4; ++nt)
#pragma unroll
            for (int q = 0; q < 4; ++q) { acc0[nt][q] = 0.f; acc1[nt][q] = 0.f; }

#pragma unroll
        for (int ks = 0; ks < 4; ++ks) {
#pragma unroll
            for (int dc = 0; dc < 3; ++dc) {
                int srow = w0 + dc + rbase;
                int ax = srow & 7;
                uint32_t aoff = (uint32_t)srow * 128u + (uint32_t)((((ks << 1) | quad) ^ ax) << 4);
                uint32_t a[4][4];
                if (v0) ldm_x4(a[0], pb[0] + aoff);
                ldm_x4(a[1], pb[1] + aoff);
                ldm_x4(a[2], pb[2] + aoff);
                if (v3) ldm_x4(a[3], pb[3] + aoff);

                uint32_t bf[3][8];
#pragma unroll
                for (int dr = 0; dr < 3; ++dr) {
                    uint32_t bt = sb + SM_W + (uint32_t)(dr * 3 + dc) * 4096u;
                    uint32_t brow = bt + (uint32_t)((ks * 16 + rbase) * 64);
                    ldm_x4_t(bf[dr],     brow + (uint32_t)(((0 | quad) ^ l3) << 4));
                    ldm_x4_t(bf[dr] + 4, brow + (uint32_t)(((2 | quad) ^ l3) << 4));
                }
#pragma unroll
                for (int nt = 0; nt < 4; ++nt) {
                    // row h: dr-th tap uses plane h-1+dr = a[dr]
                    if (v0) mma_f16(acc0[nt], a[0], bf[0] + nt * 2);
                    mma_f16(acc0[nt], a[1], bf[1] + nt * 2);
                    mma_f16(acc0[nt], a[2], bf[2] + nt * 2);
                    // row h+1: dr-th tap uses plane h+dr = a[dr+1]
                    mma_f16(acc1[nt], a[1], bf[0] + nt * 2);
                    mma_f16(acc1[nt], a[2], bf[1] + nt * 2);
                    if (v3) mma_f16(acc1[nt], a[3], bf[2] + nt * 2);
                }
            }
        }

        // epilogue: rows h and h+1
        int wcol = W0 + w0 + (lane >> 2);
#pragma unroll
        for (int nt = 0; nt < 4; ++nt) {
            int o = o0 + nt * 8 + l3 * 2;
            float* p0 = out + (((size_t)b * OUTC + o) * HH + h) * WW + wcol;
            float* p1 = p0 + (size_t)HH * WW;
            p0[0] = acc0[nt][0];
            p1[0] = acc0[nt][1];
            p0[8] = acc0[nt][2];
            p1[8] = acc0[nt][3];
            p0[WW]     = acc1[nt][0];
            p1[WW]     = acc1[nt][1];
            p0[WW + 8] = acc1[nt][2];
            p1[WW + 8] = acc1[nt][3];
        }

        // all warps done reading the retiring slots before reloading them
        __syncthreads();
        int np = 0;
        if (hp < 3) {
            np = (h + 4 < HH) ? 2 : 1;   // h+3 always valid when hp<3
            if (tid == 0) {
                MBAR_EXPECT_TX(sb, (uint32_t)(np * SLOT));
                int p = h + 3;
                BULK_G2S(sb + SM_X + (uint32_t)(p & 3) * SLOT, xh + (size_t)p * PSIZE, (uint32_t)SLOT, sb);
                if (np == 2) {
                    p = h + 4;
                    BULK_G2S(sb + SM_X + (uint32_t)(p & 3) * SLOT, xh + (size_t)p * PSIZE, (uint32_t)SLOT, sb);
                }
            }
        }
        pending = (np > 0);
    }
}

// ---------------------------------------------------------------------------
extern "C" void kernel_launch(void* const* d_in, const int* in_sizes, int n_in,
                              void* d_out, int out_size) {
    const float* x  = (const float*)d_in[0];
    const float* W1 = (const float*)d_in[1];
    const float* b1 = (const float*)d_in[2];
    const float* W2 = (const float*)d_in[3];
    const float* b2 = (const float*)d_in[4];
    float* out = (float*)d_out;

    cudaFuncSetAttribute(conv_kernel, cudaFuncAttributeMaxDynamicSharedMemorySize, SM_TOTAL);

    zero_stats_kernel<<<8, 256>>>();
    prep_kernel<<<dim3(HH, BB), 256>>>(x);
    hidden_kernel<<<BB, HID>>>(W1, b1);
    wgen_kernel<<<dim3(72, 4), 256>>>(W2, b2);
    conv_kernel<<<dim3(4, 16, BB), 128, SM_TOTAL>>>(out);
}

// round 14
// speedup vs baseline: 1.4591x; 1.0211x over previous
#include <cuda_runtime.h>
#include <cuda_fp16.h>
#include <cstdint>

#define BB   32
#define CC   64
#define HH   128
#define WW   128
#define OUTC 64
#define HID  128
#define WSZ  (OUTC * CC * 9)      // 36864

// NHWC planes with halo rows: per (b,h): 130 rows (w=-1..128) x 64 c, fp16
#define PROW   64                 // elems per row (128B)
#define PSIZE  (130 * PROW)       // 8320 elems per plane
#define PBYTES (PSIZE * 2)
// Weights per (b, o-half): [9 tap][64 c][32 o'] fp16 = 18432 elems
#define WTILE  (64 * 32)
#define WSLICE (9 * WTILE)        // 18432

// ---------------------------------------------------------------------------
// Device scratch (static globals — no allocation allowed)
// ---------------------------------------------------------------------------
__device__ float g_rowsum[BB * HH * CC];    // per-(b,h) channel sums
__device__ float g_hiddenT[HID * BB];       // transposed: [k][sample]
__device__ __align__(128) uint16_t g_wt[(size_t)BB * 2 * WSLICE];
__device__ __align__(128) uint16_t g_xhi[(size_t)BB * HH * PSIZE];

// ---------------------------------------------------------------------------
// PTX helpers
// ---------------------------------------------------------------------------
__device__ __forceinline__ uint32_t smem_u32(const void* p) {
    uint32_t a;
    asm("{ .reg .u64 t; cvta.to.shared.u64 t, %1; cvt.u32.u64 %0, t; }" : "=r"(a) : "l"(p));
    return a;
}
#define MBAR_INIT(a, n) asm volatile("mbarrier.init.shared.b64 [%0], %1;" :: "r"(a), "r"(n) : "memory")
#define MBAR_EXPECT_TX(a, b) asm volatile("mbarrier.arrive.expect_tx.shared.b64 _, [%0], %1;" :: "r"(a), "r"(b) : "memory")
#define MBAR_WAIT(a, ph) do {                                                         \
    uint32_t _m = (a), _p = (ph), _d;                                                 \
    asm volatile("{\n\t.reg .pred p;\n\t"                                             \
        "mbarrier.try_wait.parity.acquire.cta.shared::cta.b64 p, [%1], %2;\n\t"       \
        "selp.b32 %0, 1, 0, p;\n\t}" : "=r"(_d) : "r"(_m), "r"(_p) : "memory");       \
    if (!_d) {                                                                        \
        asm volatile("{\n\t.reg .pred P1;\n\t"                                        \
            "WL_%=:\n\t"                                                              \
            "mbarrier.try_wait.parity.acquire.cta.shared::cta.b64 P1, [%0], %1, 0x989680;\n\t" \
            "@P1 bra.uni WD_%=;\n\t"                                                  \
            "bra.uni WL_%=;\n\t"                                                      \
            "WD_%=:\n\t}" :: "r"(_m), "r"(_p) : "memory");                            \
    }                                                                                 \
} while (0)
#define BULK_G2S(dst, src, bytes, mbar)                                               \
    asm volatile("cp.async.bulk.shared::cta.global.mbarrier::complete_tx::bytes "      \
                 "[%0], [%1], %2, [%3];"                                               \
                 :: "r"(dst), "l"(src), "r"(bytes), "r"(mbar) : "memory")

__device__ __forceinline__ void ldm_x4(uint32_t* r, uint32_t addr) {
    asm volatile("ldmatrix.sync.aligned.m8n8.x4.shared.b16 {%0,%1,%2,%3}, [%4];"
                 : "=r"(r[0]), "=r"(r[1]), "=r"(r[2]), "=r"(r[3]) : "r"(addr));
}
__device__ __forceinline__ void ldm_x4_t(uint32_t* r, uint32_t addr) {
    asm volatile("ldmatrix.sync.aligned.m8n8.x4.trans.shared.b16 {%0,%1,%2,%3}, [%4];"
                 : "=r"(r[0]), "=r"(r[1]), "=r"(r[2]), "=r"(r[3]) : "r"(addr));
}
__device__ __forceinline__ void mma_f16(float* d, const uint32_t* a, const uint32_t* b) {
    asm volatile("mma.sync.aligned.m16n8k16.row.col.f32.f16.f16.f32 "
                 "{%0,%1,%2,%3}, {%4,%5,%6,%7}, {%8,%9}, {%0,%1,%2,%3};"
                 : "+f"(d[0]), "+f"(d[1]), "+f"(d[2]), "+f"(d[3])
                 : "r"(a[0]), "r"(a[1]), "r"(a[2]), "r"(a[3]), "r"(b[0]), "r"(b[1]));
}

// ---------------------------------------------------------------------------
// Kernel 1: prep — NCHW fp32 -> halo'd NHWC fp16 (chunk-swizzled) + row sums
// grid (h=128, b=32), 256 threads.  No atomics: plain row-sum store.
// ---------------------------------------------------------------------------
__global__ __launch_bounds__(256) void prep_kernel(const float* __restrict__ x) {
    int h = blockIdx.x, b = blockIdx.y;
    __shared__ float s[CC * 129];
    const float* xb = x + (size_t)b * CC * HH * WW + (size_t)h * WW;
    int t = threadIdx.x;
#pragma unroll
    for (int i = 0; i < 32; ++i) {
        int idx = i * 256 + t;
        int c = idx >> 7, w = idx & 127;
        s[c * 129 + w] = xb[(size_t)c * (HH * WW) + w];
    }
    __syncthreads();
    if (t < CC) {
        float sum = 0.f;
#pragma unroll 8
        for (int w = 0; w < WW; ++w) sum += s[t * 129 + w];
        g_rowsum[((size_t)b * HH + h) * CC + t] = sum;
    }
    int w = t >> 1, half = t & 1;
    __align__(16) uint16_t hbuf[32];
#pragma unroll
    for (int e = 0; e < 32; ++e) {
        __half hv = __float2half_rn(s[(half * 32 + e) * 129 + w]);
        hbuf[e] = *reinterpret_cast<uint16_t*>(&hv);
    }
    size_t rowbase = ((size_t)b * HH + h) * PSIZE + (size_t)(w + 1) * PROW;
    uint16_t* dh = g_xhi + rowbase;
    int ph = (w + 1) & 7;
#pragma unroll
    for (int g = 0; g < 4; ++g) {
        int chunk = (half * 4 + g) ^ ph;
        *reinterpret_cast<uint4*>(dh + chunk * 8) = *reinterpret_cast<const uint4*>(hbuf + g * 8);
    }
    if (t < 16) {
        int reg = t >> 3, ch = t & 7;
        uint16_t* base = g_xhi + ((size_t)b * HH + h) * PSIZE
                       + (reg ? (size_t)129 * PROW : 0) + ch * 8;
        *reinterpret_cast<uint4*>(base) = make_uint4(0u, 0u, 0u, 0u);
    }
}

// ---------------------------------------------------------------------------
// Kernel 2: hiddenT[k][b] = relu(mean @ W1 + b1); reduces row sums first.
// grid 32, block 128.
// ---------------------------------------------------------------------------
__global__ void hidden_kernel(const float* __restrict__ W1, const float* __restrict__ b1) {
    int b = blockIdx.x;
    __shared__ float s[CC];
    int t = threadIdx.x;
    if (t < CC) {
        float sum = 0.f;
        const float* rs = g_rowsum + (size_t)b * HH * CC + t;
#pragma unroll 8
        for (int h = 0; h < HH; ++h) sum += rs[h * CC];
        s[t] = sum * (1.0f / (HH * WW));
    }
    __syncthreads();
    float acc = b1[t];
#pragma unroll 8
    for (int c = 0; c < CC; ++c) acc += s[c] * W1[c * HID + t];
    g_hiddenT[t * BB + b] = fmaxf(acc, 0.0f);
}

// ---------------------------------------------------------------------------
// Kernel 3: wgen — W2 read exactly ONCE.
// grid 288, block 256.  Block covers 128 j-columns; thread = (col, k-half).
// acc = all 32 samples in registers; hidden broadcast from smem.
// Cross-k-half reduction through padded smem, then bias + fp16 + scatter.
// Output layout identical to R13: [b][oh][tap][c][o'], o' chunk-swizzled.
// ---------------------------------------------------------------------------
__global__ __launch_bounds__(256) void wgen_kernel(const float* __restrict__ W2, const float* __restrict__ b2) {
    __shared__ __align__(16) float sh[HID][BB];   // [k][sample], 16KB
    __shared__ float red[128][BB + 1];            // padded, ~16.5KB
    int tid = threadIdx.x;
    for (int i = tid; i < HID * BB; i += 256)
        sh[i >> 5][i & 31] = g_hiddenT[i];
    __syncthreads();

    int col = tid & 127;
    int kh = tid >> 7;                 // 0: k 0..63, 1: k 64..127
    int j = blockIdx.x * 128 + col;
    const float* w2p = W2 + (size_t)(kh * 64) * WSZ + j;

    float acc[BB];
#pragma unroll
    for (int s2 = 0; s2 < BB; ++s2) acc[s2] = 0.f;

#pragma unroll 4
    for (int kk = 0; kk < 64; ++kk) {
        float wv = w2p[(size_t)kk * WSZ];
        int k = kh * 64 + kk;
        const float4* hp = reinterpret_cast<const float4*>(&sh[k][0]);
#pragma unroll
        for (int g = 0; g < 8; ++g) {
            float4 hv = hp[g];
            acc[g * 4 + 0] = fmaf(hv.x, wv, acc[g * 4 + 0]);
            acc[g * 4 + 1] = fmaf(hv.y, wv, acc[g * 4 + 1]);
            acc[g * 4 + 2] = fmaf(hv.z, wv, acc[g * 4 + 2]);
            acc[g * 4 + 3] = fmaf(hv.w, wv, acc[g * 4 + 3]);
        }
    }

    if (kh == 1) {
#pragma unroll
        for (int s2 = 0; s2 < BB; ++s2) red[col][s2] = acc[s2];
    }
    __syncthreads();
    if (kh == 0) {
        float bias = b2[j];
        int o = j / (CC * 9);
        int rem = j % (CC * 9);
        int c = rem / 9;
        int k9 = rem % 9;
        int oh = o >> 5, ol = o & 31;
        int op = (((ol >> 3) ^ (c & 3)) << 3) | (ol & 7);
        size_t base0 = (((size_t)oh * 9 + k9) * 64 + c) * 32 + op;   // + s*2*WSLICE
#pragma unroll
        for (int s2 = 0; s2 < BB; ++s2) {
            float v = acc[s2] + red[col][s2] + bias;
            __half hv = __float2half_rn(v);
            g_wt[(size_t)s2 * 2 * WSLICE + base0] = *reinterpret_cast<uint16_t*>(&hv);
        }
    }
}

// ---------------------------------------------------------------------------
// Kernel 4: conv as implicit GEMM on mma.sync fp16, h-PAIR blocked.
// (unchanged from R13 — at the HMMA issue floor)
// ---------------------------------------------------------------------------
#define SM_W     128
#define SM_X     (128 + 36864)           // 36992
#define SLOT     (66 * 128)              // 8448
#define SM_TOTAL (36992 + 4 * SLOT)      // 70784

__global__ __launch_bounds__(128, 3)
void conv_kernel(float* __restrict__ out) {
    extern __shared__ char smem[];
    uint32_t sb = smem_u32(smem);
    int b = blockIdx.z;
    int h0 = blockIdx.y * 8;
    int oh = blockIdx.x & 1, wh = blockIdx.x >> 1;
    int o0 = oh * 32, W0 = wh * 64;
    int tid = threadIdx.x;
    int lane = tid & 31, wid = tid >> 5;

    if (tid == 0) {
        MBAR_INIT(sb, 1);
        asm volatile("fence.proxy.async.shared::cta;" ::: "memory");
    }
    __syncthreads();

    const uint16_t* xh = g_xhi + (size_t)b * HH * PSIZE + (size_t)W0 * PROW;

    if (tid == 0) {
        uint32_t bytes = 2 * WSLICE;
        for (int d = 0; d < 4; ++d) {
            int p = h0 - 1 + d;
            if (p >= 0 && p < HH) bytes += SLOT;
        }
        MBAR_EXPECT_TX(sb, bytes);
        BULK_G2S(sb + SM_W, g_wt + ((size_t)b * 2 + oh) * WSLICE, 2u * WSLICE, sb);
        for (int d = 0; d < 4; ++d) {
            int p = h0 - 1 + d;
            if (p < 0 || p >= HH) continue;
            BULK_G2S(sb + SM_X + (uint32_t)(p & 3) * SLOT, xh + (size_t)p * PSIZE, (uint32_t)SLOT, sb);
        }
    }

    int lph = 0;
    bool pending = true;
    int w0 = wid * 16;
    int r7 = lane & 7, half = (lane >> 3) & 1, quad = lane >> 4, l3 = lane & 3;
    int rbase = r7 + half * 8;

    for (int hp = 0; hp < 4; ++hp) {
        int h = h0 + hp * 2;
        if (pending) { MBAR_WAIT(sb, lph); lph ^= 1; }

        bool v0 = (h - 1 >= 0);
        bool v3 = (h + 2 < HH);
        uint32_t pb[4];
#pragma unroll
        for (int q = 0; q < 4; ++q)
            pb[q] = sb + SM_X + (uint32_t)((h - 1 + q) & 3) * SLOT;

        float acc0[4][4], acc1[4][4];
#pragma unroll
        for (int nt = 0; nt < 4; ++nt)
#pragma unroll
            for (int q = 0; q < 4; ++q) { acc0[nt][q] = 0.f; acc1[nt][q] = 0.f; }

#pragma unroll
        for (int ks = 0; ks < 4; ++ks) {
#pragma unroll
            for (int dc = 0; dc < 3; ++dc) {
                int srow = w0 + dc + rbase;
                int ax = srow & 7;
                uint32_t aoff = (uint32_t)srow * 128u + (uint32_t)((((ks << 1) | quad) ^ ax) << 4);
                uint32_t a[4][4];
                if (v0) ldm_x4(a[0], pb[0] + aoff);
                ldm_x4(a[1], pb[1] + aoff);
                ldm_x4(a[2], pb[2] + aoff);
                if (v3) ldm_x4(a[3], pb[3] + aoff);

                uint32_t bf[3][8];
#pragma unroll
                for (int dr = 0; dr < 3; ++dr) {
                    uint32_t bt = sb + SM_W + (uint32_t)(dr * 3 + dc) * 4096u;
                    uint32_t brow = bt + (uint32_t)((ks * 16 + rbase) * 64);
                    ldm_x4_t(bf[dr],     brow + (uint32_t)(((0 | quad) ^ l3) << 4));
                    ldm_x4_t(bf[dr] + 4, brow + (uint32_t)(((2 | quad) ^ l3) << 4));
                }
#pragma unroll
                for (int nt = 0; nt < 4; ++nt) {
                    if (v0) mma_f16(acc0[nt], a[0], bf[0] + nt * 2);
                    mma_f16(acc0[nt], a[1], bf[1] + nt * 2);
                    mma_f16(acc0[nt], a[2], bf[2] + nt * 2);
                    mma_f16(acc1[nt], a[1], bf[0] + nt * 2);
                    mma_f16(acc1[nt], a[2], bf[1] + nt * 2);
                    if (v3) mma_f16(acc1[nt], a[3], bf[2] + nt * 2);
                }
            }
        }

        int wcol = W0 + w0 + (lane >> 2);
#pragma unroll
        for (int nt = 0; nt < 4; ++nt) {
            int o = o0 + nt * 8 + l3 * 2;
            float* p0 = out + (((size_t)b * OUTC + o) * HH + h) * WW + wcol;
            float* p1 = p0 + (size_t)HH * WW;
            p0[0] = acc0[nt][0];
            p1[0] = acc0[nt][1];
            p0[8] = acc0[nt][2];
            p1[8] = acc0[nt][3];
            p0[WW]     = acc1[nt][0];
            p1[WW]     = acc1[nt][1];
            p0[WW + 8] = acc1[nt][2];
            p1[WW + 8] = acc1[nt][3];
        }

        __syncthreads();
        int np = 0;
        if (hp < 3) {
            np = (h + 4 < HH) ? 2 : 1;
            if (tid == 0) {
                MBAR_EXPECT_TX(sb, (uint32_t)(np * SLOT));
                int p = h + 3;
                BULK_G2S(sb + SM_X + (uint32_t)(p & 3) * SLOT, xh + (size_t)p * PSIZE, (uint32_t)SLOT, sb);
                if (np == 2) {
                    p = h + 4;
                    BULK_G2S(sb + SM_X + (uint32_t)(p & 3) * SLOT, xh + (size_t)p * PSIZE, (uint32_t)SLOT, sb);
                }
            }
        }
        pending = (np > 0);
    }
}

// ---------------------------------------------------------------------------
extern "C" void kernel_launch(void* const* d_in, const int* in_sizes, int n_in,
                              void* d_out, int out_size) {
    const float* x  = (const float*)d_in[0];
    const float* W1 = (const float*)d_in[1];
    const float* b1 = (const float*)d_in[2];
    const float* W2 = (const float*)d_in[3];
    const float* b2 = (const float*)d_in[4];
    float* out = (float*)d_out;

    cudaFuncSetAttribute(conv_kernel, cudaFuncAttributeMaxDynamicSharedMemorySize, SM_TOTAL);

    prep_kernel<<<dim3(HH, BB), 256>>>(x);
    hidden_kernel<<<BB, HID>>>(W1, b1);
    wgen_kernel<<<288, 256>>>(W2, b2);
    conv_kernel<<<dim3(4, 16, BB), 128, SM_TOTAL>>>(out);
}

// round 16
// speedup vs baseline: 1.6092x; 1.1029x over previous
#include <cuda_runtime.h>
#include <cuda_fp16.h>
#include <cstdint>

#define BB   32
#define CC   64
#define HH   128
#define WW   128
#define OUTC 64
#define HID  128
#define WSZ  (OUTC * CC * 9)      // 36864

// NHWC planes with halo rows: per (b,h): 130 rows (w=-1..128) x 64 c, fp16
#define PROW   64
#define PSIZE  (130 * PROW)
#define PBYTES (PSIZE * 2)
// Weights per (b, o-half): [9 tap][64 c][32 o'] fp16 = 18432 elems
#define WTILE  (64 * 32)
#define WSLICE (9 * WTILE)        // 18432 elems = 36864 B per o-half

// ---------------------------------------------------------------------------
__device__ float g_rowsum[BB * HH * CC];
__device__ float g_hiddenT[HID * BB];
__device__ __align__(128) uint16_t g_wt[(size_t)BB * 2 * WSLICE];
__device__ __align__(128) uint16_t g_xhi[(size_t)BB * HH * PSIZE];

// ---------------------------------------------------------------------------
__device__ __forceinline__ uint32_t smem_u32(const void* p) {
    uint32_t a;
    asm("{ .reg .u64 t; cvta.to.shared.u64 t, %1; cvt.u32.u64 %0, t; }" : "=r"(a) : "l"(p));
    return a;
}
#define MBAR_INIT(a, n) asm volatile("mbarrier.init.shared.b64 [%0], %1;" :: "r"(a), "r"(n) : "memory")
#define MBAR_EXPECT_TX(a, b) asm volatile("mbarrier.arrive.expect_tx.shared.b64 _, [%0], %1;" :: "r"(a), "r"(b) : "memory")
#define MBAR_WAIT(a, ph) do {                                                         \
    uint32_t _m = (a), _p = (ph), _d;                                                 \
    asm volatile("{\n\t.reg .pred p;\n\t"                                             \
        "mbarrier.try_wait.parity.acquire.cta.shared::cta.b64 p, [%1], %2;\n\t"       \
        "selp.b32 %0, 1, 0, p;\n\t}" : "=r"(_d) : "r"(_m), "r"(_p) : "memory");       \
    if (!_d) {                                                                        \
        asm volatile("{\n\t.reg .pred P1;\n\t"                                        \
            "WL_%=:\n\t"                                                              \
            "mbarrier.try_wait.parity.acquire.cta.shared::cta.b64 P1, [%0], %1, 0x989680;\n\t" \
            "@P1 bra.uni WD_%=;\n\t"                                                  \
            "bra.uni WL_%=;\n\t"                                                      \
            "WD_%=:\n\t}" :: "r"(_m), "r"(_p) : "memory");                            \
    }                                                                                 \
} while (0)
#define BULK_G2S(dst, src, bytes, mbar)                                               \
    asm volatile("cp.async.bulk.shared::cta.global.mbarrier::complete_tx::bytes "      \
                 "[%0], [%1], %2, [%3];"                                               \
                 :: "r"(dst), "l"(src), "r"(bytes), "r"(mbar) : "memory")

__device__ __forceinline__ void ldm_x4(uint32_t* r, uint32_t addr) {
    asm volatile("ldmatrix.sync.aligned.m8n8.x4.shared.b16 {%0,%1,%2,%3}, [%4];"
                 : "=r"(r[0]), "=r"(r[1]), "=r"(r[2]), "=r"(r[3]) : "r"(addr));
}
__device__ __forceinline__ void ldm_x4_t(uint32_t* r, uint32_t addr) {
    asm volatile("ldmatrix.sync.aligned.m8n8.x4.trans.shared.b16 {%0,%1,%2,%3}, [%4];"
                 : "=r"(r[0]), "=r"(r[1]), "=r"(r[2]), "=r"(r[3]) : "r"(addr));
}
__device__ __forceinline__ void mma_f16(float* d, const uint32_t* a, const uint32_t* b) {
    asm volatile("mma.sync.aligned.m16n8k16.row.col.f32.f16.f16.f32 "
                 "{%0,%1,%2,%3}, {%4,%5,%6,%7}, {%8,%9}, {%0,%1,%2,%3};"
                 : "+f"(d[0]), "+f"(d[1]), "+f"(d[2]), "+f"(d[3])
                 : "r"(a[0]), "r"(a[1]), "r"(a[2]), "r"(a[3]), "r"(b[0]), "r"(b[1]));
}

// ---------------------------------------------------------------------------
// Kernel 1: prep (unchanged from R14)
// ---------------------------------------------------------------------------
__global__ __launch_bounds__(256) void prep_kernel(const float* __restrict__ x) {
    int h = blockIdx.x, b = blockIdx.y;
    __shared__ float s[CC * 129];
    const float* xb = x + (size_t)b * CC * HH * WW + (size_t)h * WW;
    int t = threadIdx.x;
#pragma unroll
    for (int i = 0; i < 32; ++i) {
        int idx = i * 256 + t;
        int c = idx >> 7, w = idx & 127;
        s[c * 129 + w] = xb[(size_t)c * (HH * WW) + w];
    }
    __syncthreads();
    if (t < CC) {
        float sum = 0.f;
#pragma unroll 8
        for (int w = 0; w < WW; ++w) sum += s[t * 129 + w];
        g_rowsum[((size_t)b * HH + h) * CC + t] = sum;
    }
    int w = t >> 1, half = t & 1;
    __align__(16) uint16_t hbuf[32];
#pragma unroll
    for (int e = 0; e < 32; ++e) {
        __half hv = __float2half_rn(s[(half * 32 + e) * 129 + w]);
        hbuf[e] = *reinterpret_cast<uint16_t*>(&hv);
    }
    size_t rowbase = ((size_t)b * HH + h) * PSIZE + (size_t)(w + 1) * PROW;
    uint16_t* dh = g_xhi + rowbase;
    int ph = (w + 1) & 7;
#pragma unroll
    for (int g = 0; g < 4; ++g) {
        int chunk = (half * 4 + g) ^ ph;
        *reinterpret_cast<uint4*>(dh + chunk * 8) = *reinterpret_cast<const uint4*>(hbuf + g * 8);
    }
    if (t < 16) {
        int reg = t >> 3, ch = t & 7;
        uint16_t* base = g_xhi + ((size_t)b * HH + h) * PSIZE
                       + (reg ? (size_t)129 * PROW : 0) + ch * 8;
        *reinterpret_cast<uint4*>(base) = make_uint4(0u, 0u, 0u, 0u);
    }
}

// ---------------------------------------------------------------------------
// Kernel 2: hidden (unchanged from R14)
// ---------------------------------------------------------------------------
__global__ void hidden_kernel(const float* __restrict__ W1, const float* __restrict__ b1) {
    int b = blockIdx.x;
    __shared__ float s[CC];
    int t = threadIdx.x;
    if (t < CC) {
        float sum = 0.f;
        const float* rs = g_rowsum + (size_t)b * HH * CC + t;
#pragma unroll 8
        for (int h = 0; h < HH; ++h) sum += rs[h * CC];
        s[t] = sum * (1.0f / (HH * WW));
    }
    __syncthreads();
    float acc = b1[t];
#pragma unroll 8
    for (int c = 0; c < CC; ++c) acc += s[c] * W1[c * HID + t];
    g_hiddenT[t * BB + b] = fmaxf(acc, 0.0f);
}

// ---------------------------------------------------------------------------
// Kernel 3: wgen (unchanged from R14 — W2 read once)
// ---------------------------------------------------------------------------
__global__ __launch_bounds__(256) void wgen_kernel(const float* __restrict__ W2, const float* __restrict__ b2) {
    __shared__ __align__(16) float sh[HID][BB];
    __shared__ float red[128][BB + 1];
    int tid = threadIdx.x;
    for (int i = tid; i < HID * BB; i += 256)
        sh[i >> 5][i & 31] = g_hiddenT[i];
    __syncthreads();

    int col = tid & 127;
    int kh = tid >> 7;
    int j = blockIdx.x * 128 + col;
    const float* w2p = W2 + (size_t)(kh * 64) * WSZ + j;

    float acc[BB];
#pragma unroll
    for (int s2 = 0; s2 < BB; ++s2) acc[s2] = 0.f;

#pragma unroll 4
    for (int kk = 0; kk < 64; ++kk) {
        float wv = w2p[(size_t)kk * WSZ];
        int k = kh * 64 + kk;
        const float4* hp = reinterpret_cast<const float4*>(&sh[k][0]);
#pragma unroll
        for (int g = 0; g < 8; ++g) {
            float4 hv = hp[g];
            acc[g * 4 + 0] = fmaf(hv.x, wv, acc[g * 4 + 0]);
            acc[g * 4 + 1] = fmaf(hv.y, wv, acc[g * 4 + 1]);
            acc[g * 4 + 2] = fmaf(hv.z, wv, acc[g * 4 + 2]);
            acc[g * 4 + 3] = fmaf(hv.w, wv, acc[g * 4 + 3]);
        }
    }

    if (kh == 1) {
#pragma unroll
        for (int s2 = 0; s2 < BB; ++s2) red[col][s2] = acc[s2];
    }
    __syncthreads();
    if (kh == 0) {
        float bias = b2[j];
        int o = j / (CC * 9);
        int rem = j % (CC * 9);
        int c = rem / 9;
        int k9 = rem % 9;
        int oh = o >> 5, ol = o & 31;
        int op = (((ol >> 3) ^ (c & 3)) << 3) | (ol & 7);
        size_t base0 = (((size_t)oh * 9 + k9) * 64 + c) * 32 + op;
#pragma unroll
        for (int s2 = 0; s2 < BB; ++s2) {
            float v = acc[s2] + red[col][s2] + bias;
            __half hv = __float2half_rn(v);
            g_wt[(size_t)s2 * 2 * WSLICE + base0] = *reinterpret_cast<uint16_t*>(&hv);
        }
    }
}

// ---------------------------------------------------------------------------
// Kernel 4: conv — m32n32 warps to halve B ldmatrix traffic per output.
// grid (wh=2, htile=16, b=32) = 1024 CTAs, 128 threads, 2 CTAs/SM.
// CTA: 64 w x 64 o x 8 h (4 h-pairs).  Warp (mblk = wid&1, nblk = wid>>1):
// m32 (w-rows mblk*32..+31, 2 m16 frags) x n32 (o nblk*32..+31).
// Per (ks,dc): A 8 ldm (4 planes x 2 mh), B 6 ldm (3 dr), 48 HMMA.
// ---------------------------------------------------------------------------
#define SM_W     128
#define SM_X     (128 + 73728)           // 73856
#define SLOT     (66 * 128)              // 8448
#define SM_TOTAL (73856 + 4 * SLOT)      // 107648

__global__ __launch_bounds__(128, 2)
void conv_kernel(float* __restrict__ out) {
    extern __shared__ char smem[];
    uint32_t sb = smem_u32(smem);
    int b = blockIdx.z;
    int h0 = blockIdx.y * 8;
    int wh = blockIdx.x;
    int W0 = wh * 64;
    int tid = threadIdx.x;
    int lane = tid & 31, wid = tid >> 5;
    int mblk = wid & 1, nblk = wid >> 1;

    if (tid == 0) {
        MBAR_INIT(sb, 1);
        asm volatile("fence.proxy.async.shared::cta;" ::: "memory");
    }
    __syncthreads();

    const uint16_t* xh = g_xhi + (size_t)b * HH * PSIZE + (size_t)W0 * PROW;

    // prologue: both W o-slices (contiguous) + planes h0-1..h0+2
    if (tid == 0) {
        uint32_t bytes = 4 * WSLICE;   // 73728 B
        for (int d = 0; d < 4; ++d) {
            int p = h0 - 1 + d;
            if (p >= 0 && p < HH) bytes += SLOT;
        }
        MBAR_EXPECT_TX(sb, bytes);
        BULK_G2S(sb + SM_W, g_wt + (size_t)b * 2 * WSLICE, 4u * WSLICE, sb);
        for (int d = 0; d < 4; ++d) {
            int p = h0 - 1 + d;
            if (p < 0 || p >= HH) continue;
            BULK_G2S(sb + SM_X + (uint32_t)(p & 3) * SLOT, xh + (size_t)p * PSIZE, (uint32_t)SLOT, sb);
        }
    }

    int lph = 0;
    bool pending = true;
    int r7 = lane & 7, half = (lane >> 3) & 1, quad = lane >> 4, l3 = lane & 3;
    int rbase = r7 + half * 8;
    uint32_t wslice = sb + SM_W + (uint32_t)nblk * 36864u;

    for (int hp = 0; hp < 4; ++hp) {
        int h = h0 + hp * 2;
        if (pending) { MBAR_WAIT(sb, lph); lph ^= 1; }

        bool v0 = (h - 1 >= 0);
        bool v3 = (h + 2 < HH);
        uint32_t pb[4];
#pragma unroll
        for (int q = 0; q < 4; ++q)
            pb[q] = sb + SM_X + (uint32_t)((h - 1 + q) & 3) * SLOT;

        float acc[2][2][4][4];   // [row][mh][nt][4]
#pragma unroll
        for (int r = 0; r < 2; ++r)
#pragma unroll
            for (int mh = 0; mh < 2; ++mh)
#pragma unroll
                for (int nt = 0; nt < 4; ++nt)
#pragma unroll
                    for (int q = 0; q < 4; ++q) acc[r][mh][nt][q] = 0.f;

#pragma unroll
        for (int ks = 0; ks < 4; ++ks) {
#pragma unroll
            for (int dc = 0; dc < 3; ++dc) {
                uint32_t a[4][2][4];
#pragma unroll
                for (int mh = 0; mh < 2; ++mh) {
                    int srow = mblk * 32 + mh * 16 + dc + rbase;
                    int ax = srow & 7;
                    uint32_t aoff = (uint32_t)srow * 128u
                                  + (uint32_t)((((ks << 1) | quad) ^ ax) << 4);
                    if (v0) ldm_x4(a[0][mh], pb[0] + aoff);
                    ldm_x4(a[1][mh], pb[1] + aoff);
                    ldm_x4(a[2][mh], pb[2] + aoff);
                    if (v3) ldm_x4(a[3][mh], pb[3] + aoff);
                }
                uint32_t bf[3][8];
#pragma unroll
                for (int dr = 0; dr < 3; ++dr) {
                    uint32_t brow = wslice + (uint32_t)(dr * 3 + dc) * 4096u
                                  + (uint32_t)((ks * 16 + rbase) * 64);
                    ldm_x4_t(bf[dr],     brow + (uint32_t)(((0 | quad) ^ l3) << 4));
                    ldm_x4_t(bf[dr] + 4, brow + (uint32_t)(((2 | quad) ^ l3) << 4));
                }
#pragma unroll
                for (int mh = 0; mh < 2; ++mh)
#pragma unroll
                    for (int nt = 0; nt < 4; ++nt) {
                        if (v0) mma_f16(acc[0][mh][nt], a[0][mh], bf[0] + nt * 2);
                        mma_f16(acc[0][mh][nt], a[1][mh], bf[1] + nt * 2);
                        mma_f16(acc[0][mh][nt], a[2][mh], bf[2] + nt * 2);
                        mma_f16(acc[1][mh][nt], a[1][mh], bf[0] + nt * 2);
                        mma_f16(acc[1][mh][nt], a[2][mh], bf[1] + nt * 2);
                        if (v3) mma_f16(acc[1][mh][nt], a[3][mh], bf[2] + nt * 2);
                    }
            }
        }

        // epilogue: rows h, h+1; w = W0 + mblk*32 + mh*16 + (lane>>2) (+8)
#pragma unroll
        for (int mh = 0; mh < 2; ++mh) {
            int wcol = W0 + mblk * 32 + mh * 16 + (lane >> 2);
#pragma unroll
            for (int nt = 0; nt < 4; ++nt) {
                int o = nblk * 32 + nt * 8 + l3 * 2;
                float* p0 = out + (((size_t)b * OUTC + o) * HH + h) * WW + wcol;
                float* p1 = p0 + (size_t)HH * WW;
                p0[0] = acc[0][mh][nt][0];
                p1[0] = acc[0][mh][nt][1];
                p0[8] = acc[0][mh][nt][2];
                p1[8] = acc[0][mh][nt][3];
                p0[WW]     = acc[1][mh][nt][0];
                p1[WW]     = acc[1][mh][nt][1];
                p0[WW + 8] = acc[1][mh][nt][2];
                p1[WW + 8] = acc[1][mh][nt][3];
            }
        }

        __syncthreads();
        int np = 0;
        if (hp < 3) {
            np = (h + 4 < HH) ? 2 : 1;
            if (tid == 0) {
                MBAR_EXPECT_TX(sb, (uint32_t)(np * SLOT));
                int p = h + 3;
                BULK_G2S(sb + SM_X + (uint32_t)(p & 3) * SLOT, xh + (size_t)p * PSIZE, (uint32_t)SLOT, sb);
                if (np == 2) {
                    p = h + 4;
                    BULK_G2S(sb + SM_X + (uint32_t)(p & 3) * SLOT, xh + (size_t)p * PSIZE, (uint32_t)SLOT, sb);
                }
            }
        }
        pending = (np > 0);
    }
}

// ---------------------------------------------------------------------------
extern "C" void kernel_launch(void* const* d_in, const int* in_sizes, int n_in,
                              void* d_out, int out_size) {
    const float* x  = (const float*)d_in[0];
    const float* W1 = (const float*)d_in[1];
    const float* b1 = (const float*)d_in[2];
    const float* W2 = (const float*)d_in[3];
    const float* b2 = (const float*)d_in[4];
    float* out = (float*)d_out;

    cudaFuncSetAttribute(conv_kernel, cudaFuncAttributeMaxDynamicSharedMemorySize, SM_TOTAL);

    prep_kernel<<<dim3(HH, BB), 256>>>(x);
    hidden_kernel<<<BB, HID>>>(W1, b1);
    wgen_kernel<<<288, 256>>>(W2, b2);
    conv_kernel<<<dim3(2, 16, BB), 128, SM_TOTAL>>>(out);
}